// round 5
// baseline (speedup 1.0000x reference)
#include <cuda_runtime.h>
#include <math.h>

#define BATCH   32
#define LAYERS  32
#define DIM     4096
#define SELK    24
#define NCHOICE 9
#define GS_EPS  1e-10f

#define F4_PER_LAYER (DIM / 4)      // 1024 float4 per layer

// Dependent gather, minimal traffic: read ONLY the selected 24 layers (12 MB),
// write 12 MB. Block (k, b) copies output layer k of batch b = input layer
// idx[b]+k. idx is computed per-warp via shuffle reduce; all warps' noise
// loads coalesce/merge in L1 so the block pays ~one exposed round-trip.
// Stores are streaming (.cs) so output doesn't evict the L2-resident input.

__global__ void __launch_bounds__(256)
gather_kernel(const float4* __restrict__ feats4,
              const float*  __restrict__ logits,
              const float*  __restrict__ noise,
              float* __restrict__ out) {
    const int k = blockIdx.x;            // output layer 0..23
    const int b = blockIdx.y;
    const int t = threadIdx.x;
    const int lane = t & 31;

    // ---- per-warp Gumbel argmax (lanes 0-8), first instructions issued ----
    float v  = -INFINITY;
    int   bc = lane;
    if (lane < NCHOICE) {
        float u = __ldg(&noise[b * NCHOICE + lane]);
        float g = -logf(-logf(u + GS_EPS) + GS_EPS);
        v = __ldg(&logits[lane]) + g;    // tau=1; softmax monotone -> same argmax
    }
    #pragma unroll
    for (int off = 16; off; off >>= 1) {
        float ov = __shfl_down_sync(0xffffffffu, v,  off);
        int   oc = __shfl_down_sync(0xffffffffu, bc, off);
        if (ov > v || (ov == v && oc < bc)) { v = ov; bc = oc; }  // first-max wins
    }
    const int idx = __shfl_sync(0xffffffffu, bc, 0);

    // one-hot selection_probs tail: block k==0 of each batch
    if (k == 0 && t < NCHOICE) {
        out[(size_t)BATCH * SELK * DIM + b * NCHOICE + t] =
            (t == idx) ? 1.0f : 0.0f;
    }

    // ---- copy input layer (idx + k) -> output layer k, MLP=4 ----
    const float4* __restrict__ src =
        feats4 + ((size_t)b * LAYERS + (idx + k)) * F4_PER_LAYER;
    float4* __restrict__ dst =
        (float4*)out + ((size_t)b * SELK + k) * F4_PER_LAYER;

    float4 v0 = __ldg(&src[t]);
    float4 v1 = __ldg(&src[t + 256]);
    float4 v2 = __ldg(&src[t + 512]);
    float4 v3 = __ldg(&src[t + 768]);

    __stcs(&dst[t],       v0);
    __stcs(&dst[t + 256], v1);
    __stcs(&dst[t + 512], v2);
    __stcs(&dst[t + 768], v3);
}

extern "C" void kernel_launch(void* const* d_in, const int* in_sizes, int n_in,
                              void* d_out, int out_size) {
    const float* feats  = (const float*)d_in[0];
    const float* logits = (const float*)d_in[1];
    const float* noise  = (const float*)d_in[2];
    float*       out    = (float*)d_out;

    dim3 grid(SELK, BATCH);              // (24, 32) = 768 blocks
    gather_kernel<<<grid, 256>>>((const float4*)feats, logits, noise, out);
}